// round 2
// baseline (speedup 1.0000x reference)
#include <cuda_runtime.h>
#include <cuda_bf16.h>

#define NN 8192
#define TEMPER 0.2f

// Scratch (static __device__ arrays per harness rules)
static __device__ __nv_bfloat16 g_Q[(size_t)NN * NN];   // 128 MB bf16 Q for iterations
static __device__ float g_colAccS[4][NN];               // sliced accumulators (atomic contention)
static __device__ float g_V[NN];
static __device__ unsigned int g_minBits;
static __device__ double g_sum;
static __device__ double g_sumsq;
static __device__ float g_minv;
static __device__ float g_kscale;

// ---------------------------------------------------------------- init
__global__ void k_init() {
    int i = blockIdx.x * blockDim.x + threadIdx.x;
    if (i < NN) {
        g_colAccS[0][i] = 0.0f;
        g_colAccS[1][i] = 0.0f;
        g_colAccS[2][i] = 0.0f;
        g_colAccS[3][i] = 0.0f;
    }
    if (i == 0) {
        g_minBits = 0x7f800000u;  // +inf
        g_sum = 0.0;
        g_sumsq = 0.0;
    }
}

// ---------------------------------------------------------------- reduce: min / sum / sumsq
__global__ void __launch_bounds__(256) k_reduce(const float* __restrict__ c) {
    const size_t total4 = (size_t)NN * NN / 4;
    const size_t stride = (size_t)gridDim.x * blockDim.x;
    double s = 0.0, ss = 0.0;
    float mn = 3.402823466e38f;
    for (size_t i = (size_t)blockIdx.x * blockDim.x + threadIdx.x; i < total4; i += stride) {
        float4 v = reinterpret_cast<const float4*>(c)[i];
        float cs  = (v.x + v.y) + (v.z + v.w);
        float css = fmaf(v.x, v.x, fmaf(v.y, v.y, fmaf(v.z, v.z, v.w * v.w)));
        s  += (double)cs;
        ss += (double)css;
        mn = fminf(mn, fminf(fminf(v.x, v.y), fminf(v.z, v.w)));
    }
    for (int o = 16; o > 0; o >>= 1) {
        s  += __shfl_down_sync(0xffffffffu, s, o);
        ss += __shfl_down_sync(0xffffffffu, ss, o);
        mn = fminf(mn, __shfl_down_sync(0xffffffffu, mn, o));
    }
    __shared__ double sh_s[8], sh_ss[8];
    __shared__ float sh_m[8];
    int warp = threadIdx.x >> 5, lane = threadIdx.x & 31;
    if (lane == 0) { sh_s[warp] = s; sh_ss[warp] = ss; sh_m[warp] = mn; }
    __syncthreads();
    if (threadIdx.x < 8) {
        s = sh_s[threadIdx.x]; ss = sh_ss[threadIdx.x]; mn = sh_m[threadIdx.x];
        for (int o = 4; o > 0; o >>= 1) {
            s  += __shfl_down_sync(0xffu, s, o);
            ss += __shfl_down_sync(0xffu, ss, o);
            mn = fminf(mn, __shfl_down_sync(0xffu, mn, o));
        }
        if (threadIdx.x == 0) {
            atomicAdd(&g_sum, s);
            atomicAdd(&g_sumsq, ss);
            atomicMin(&g_minBits, __float_as_uint(mn));
        }
    }
}

// ---------------------------------------------------------------- scalar finalize
__global__ void k_scalars() {
    double n = (double)NN * (double)NN;
    double var = (g_sumsq - g_sum * g_sum / n) / (n - 1.0);
    float stdv = (float)sqrt(var);
    g_minv = __uint_as_float(g_minBits);
    g_kscale = 1.0f / (stdv * TEMPER);
}

// ---------------------------------------------------------------- build Q (bf16) + colsum -> V1
// grid (8, 128): blockIdx.x = 1024-col chunk, blockIdx.y = 64-row chunk; 4 cols/thread
__global__ void __launch_bounds__(256) k_build(const float* __restrict__ c) {
    const float minv = g_minv, kk = g_kscale;
    int col0 = (blockIdx.x * 256 + threadIdx.x) * 4;
    int row0 = blockIdx.y * 64;
    float a0 = 0.f, a1 = 0.f, a2 = 0.f, a3 = 0.f;
    for (int r = 0; r < 64; ++r) {
        size_t base = (size_t)(row0 + r) * NN + col0;
        float4 v = *reinterpret_cast<const float4*>(c + base);
        float q0 = __expf((minv - v.x) * kk);
        float q1 = __expf((minv - v.y) * kk);
        float q2 = __expf((minv - v.z) * kk);
        float q3 = __expf((minv - v.w) * kk);
        a0 += q0; a1 += q1; a2 += q2; a3 += q3;
        __nv_bfloat162 p0 = __floats2bfloat162_rn(q0, q1);
        __nv_bfloat162 p1 = __floats2bfloat162_rn(q2, q3);
        uint2 w;
        w.x = *reinterpret_cast<unsigned int*>(&p0);
        w.y = *reinterpret_cast<unsigned int*>(&p1);
        *reinterpret_cast<uint2*>(g_Q + base) = w;
    }
    float* ca = g_colAccS[blockIdx.y & 3];
    atomicAdd(&ca[col0 + 0], a0);
    atomicAdd(&ca[col0 + 1], a1);
    atomicAdd(&ca[col0 + 2], a2);
    atomicAdd(&ca[col0 + 3], a3);
}

// ---------------------------------------------------------------- V = B / sum(slices) ; slices = 0
__global__ void k_vfin(const float* __restrict__ B) {
    int j = blockIdx.x * blockDim.x + threadIdx.x;
    if (j < NN) {
        float s = (g_colAccS[0][j] + g_colAccS[1][j]) + (g_colAccS[2][j] + g_colAccS[3][j]);
        g_V[j] = B[j] / s;
        g_colAccS[0][j] = 0.0f;
        g_colAccS[1][j] = 0.0f;
        g_colAccS[2][j] = 0.0f;
        g_colAccS[3][j] = 0.0f;
    }
}

__device__ __forceinline__ float dot8(uint4 raw, float4 va, float4 vb) {
    float2 f0 = __bfloat1622float2(*reinterpret_cast<__nv_bfloat162*>(&raw.x));
    float2 f1 = __bfloat1622float2(*reinterpret_cast<__nv_bfloat162*>(&raw.y));
    float2 f2 = __bfloat1622float2(*reinterpret_cast<__nv_bfloat162*>(&raw.z));
    float2 f3 = __bfloat1622float2(*reinterpret_cast<__nv_bfloat162*>(&raw.w));
    float r = f0.x * va.x;
    r = fmaf(f0.y, va.y, r);
    r = fmaf(f1.x, va.z, r);
    r = fmaf(f1.y, va.w, r);
    r = fmaf(f2.x, vb.x, r);
    r = fmaf(f2.y, vb.y, r);
    r = fmaf(f3.x, vb.z, r);
    r = fmaf(f3.y, vb.w, r);
    return r;
}

// ---------------------------------------------------------------- fused Sinkhorn pass:
//   u_i = A_i / (Q~ V)_i  (per row, block-local)
//   colAcc_j += sum_i u_i * Q~_ij   (phase-2 re-read of same rows: L1/L2 hot)
// grid 2048 blocks x 512 threads; block handles 4 rows; 4 warps per row (2048-col quarters)
__global__ void __launch_bounds__(512) k_fused(const float* __restrict__ A) {
    __shared__ float sdot[16];
    __shared__ float sU[4];
    int tid = threadIdx.x;
    int warp = tid >> 5, lane = tid & 31;
    int row0 = blockIdx.x * 4;
    int rsel = warp & 3;       // which of the 4 rows
    int quarter = warp >> 2;   // which 2048-col quarter

    // ---- phase 1: dot(Q~ row, V) per row
    const __nv_bfloat16* qr = g_Q + (size_t)(row0 + rsel) * NN + quarter * 2048;
    const float* vq = g_V + quarter * 2048;
    float acc = 0.f;
#pragma unroll
    for (int i = 0; i < 8; ++i) {
        int j = lane * 8 + i * 256;
        uint4 raw = *reinterpret_cast<const uint4*>(qr + j);
        float4 va = *reinterpret_cast<const float4*>(vq + j);
        float4 vb = *reinterpret_cast<const float4*>(vq + j + 4);
        acc += dot8(raw, va, vb);
    }
    for (int o = 16; o > 0; o >>= 1)
        acc += __shfl_down_sync(0xffffffffu, acc, o);
    if (lane == 0) sdot[warp] = acc;
    __syncthreads();
    if (tid < 4) {
        float d = (sdot[tid] + sdot[tid + 4]) + (sdot[tid + 8] + sdot[tid + 12]);
        sU[tid] = __ldg(A + row0 + tid) / d;
    }
    __syncthreads();

    // ---- phase 2: colAcc_j += sum_r u_r * Q~_rj  (16 cols per thread)
    int col0 = tid * 16;
    const __nv_bfloat16* qb = g_Q + (size_t)row0 * NN + col0;
    float a[16];
#pragma unroll
    for (int i = 0; i < 16; ++i) a[i] = 0.f;
#pragma unroll
    for (int r = 0; r < 4; ++r) {
        float u = sU[r];
        uint4 ra = *reinterpret_cast<const uint4*>(qb + (size_t)r * NN);
        uint4 rb = *reinterpret_cast<const uint4*>(qb + (size_t)r * NN + 8);
        float2 f0 = __bfloat1622float2(*reinterpret_cast<__nv_bfloat162*>(&ra.x));
        float2 f1 = __bfloat1622float2(*reinterpret_cast<__nv_bfloat162*>(&ra.y));
        float2 f2 = __bfloat1622float2(*reinterpret_cast<__nv_bfloat162*>(&ra.z));
        float2 f3 = __bfloat1622float2(*reinterpret_cast<__nv_bfloat162*>(&ra.w));
        float2 f4 = __bfloat1622float2(*reinterpret_cast<__nv_bfloat162*>(&rb.x));
        float2 f5 = __bfloat1622float2(*reinterpret_cast<__nv_bfloat162*>(&rb.y));
        float2 f6 = __bfloat1622float2(*reinterpret_cast<__nv_bfloat162*>(&rb.z));
        float2 f7 = __bfloat1622float2(*reinterpret_cast<__nv_bfloat162*>(&rb.w));
        a[0]  = fmaf(f0.x, u, a[0]);   a[1]  = fmaf(f0.y, u, a[1]);
        a[2]  = fmaf(f1.x, u, a[2]);   a[3]  = fmaf(f1.y, u, a[3]);
        a[4]  = fmaf(f2.x, u, a[4]);   a[5]  = fmaf(f2.y, u, a[5]);
        a[6]  = fmaf(f3.x, u, a[6]);   a[7]  = fmaf(f3.y, u, a[7]);
        a[8]  = fmaf(f4.x, u, a[8]);   a[9]  = fmaf(f4.y, u, a[9]);
        a[10] = fmaf(f5.x, u, a[10]);  a[11] = fmaf(f5.y, u, a[11]);
        a[12] = fmaf(f6.x, u, a[12]);  a[13] = fmaf(f6.y, u, a[13]);
        a[14] = fmaf(f7.x, u, a[14]);  a[15] = fmaf(f7.y, u, a[15]);
    }
    float* ca = g_colAccS[blockIdx.x & 3];
#pragma unroll
    for (int i = 0; i < 16; ++i)
        atomicAdd(&ca[col0 + i], a[i]);
}

// ---------------------------------------------------------------- final: exact Q, fused U10, write T
__global__ void __launch_bounds__(256) k_final(const float* __restrict__ c,
                                               const float* __restrict__ A,
                                               float* __restrict__ out) {
    __shared__ float sV[NN];
    __shared__ float sred[8];
    __shared__ float sbc;
    int tid = threadIdx.x;
#pragma unroll
    for (int i = 0; i < 8; ++i)
        reinterpret_cast<float4*>(sV)[tid + i * 256] =
            reinterpret_cast<const float4*>(g_V)[tid + i * 256];
    __syncthreads();
    const float minv = g_minv, kk = g_kscale;
    for (int row = blockIdx.x; row < NN; row += gridDim.x) {
        const float4* crow = reinterpret_cast<const float4*>(c + (size_t)row * NN);
        float4 qv[8];
        float s = 0.f;
#pragma unroll
        for (int k = 0; k < 8; ++k) {
            int j = tid * 4 + k * 1024;
            float4 v  = crow[tid + k * 256];
            float4 vv = *reinterpret_cast<const float4*>(sV + j);
            float q0 = __expf((minv - v.x) * kk) * vv.x;
            float q1 = __expf((minv - v.y) * kk) * vv.y;
            float q2 = __expf((minv - v.z) * kk) * vv.z;
            float q3 = __expf((minv - v.w) * kk) * vv.w;
            qv[k].x = q0; qv[k].y = q1; qv[k].z = q2; qv[k].w = q3;
            s += (q0 + q1) + (q2 + q3);
        }
        for (int o = 16; o > 0; o >>= 1)
            s += __shfl_down_sync(0xffffffffu, s, o);
        if ((tid & 31) == 0) sred[tid >> 5] = s;
        __syncthreads();
        if (tid < 32) {
            float t = (tid < 8) ? sred[tid] : 0.f;
            for (int o = 4; o > 0; o >>= 1)
                t += __shfl_down_sync(0xffffffffu, t, o);
            if (tid == 0) sbc = __ldg(A + row) / t;
        }
        __syncthreads();
        float scale = sbc;
        float4* orow = reinterpret_cast<float4*>(out + (size_t)row * NN);
#pragma unroll
        for (int k = 0; k < 8; ++k) {
            float4 w = qv[k];
            w.x *= scale; w.y *= scale; w.z *= scale; w.w *= scale;
            orow[tid + k * 256] = w;
        }
        __syncthreads();  // protect sred/sbc reuse next row
    }
}

// ---------------------------------------------------------------- launch
extern "C" void kernel_launch(void* const* d_in, const int* in_sizes, int n_in,
                              void* d_out, int out_size) {
    const float* cdist = (const float*)d_in[0];
    const float* A     = (const float*)d_in[1];
    const float* B     = (const float*)d_in[2];
    float* out = (float*)d_out;

    k_init<<<32, 256>>>();
    k_reduce<<<1184, 256>>>(cdist);
    k_scalars<<<1, 1>>>();
    k_build<<<dim3(8, 128), 256>>>(cdist);  // Q~ (bf16), colsum -> slices
    k_vfin<<<32, 256>>>(B);                 // V1 = B / colsum(Q)
    for (int k = 1; k <= 9; ++k) {
        k_fused<<<2048, 512>>>(A);          // U_k = A/(Q~ V_k); slices = Q~^T U_k
        k_vfin<<<32, 256>>>(B);             // V_{k+1} = B / slices
    }
    // U10 fused into output: exact fp32 Q, T = (A_i/(Q V10)_i) * Q_ij * V10_j
    k_final<<<444, 256>>>(cdist, A, out);
}

// round 3
// speedup vs baseline: 2.1946x; 2.1946x over previous
#include <cuda_runtime.h>
#include <cuda_bf16.h>
#include <cuda_fp8.h>

#define NN 8192
#define TEMPER 0.2f

// Scratch (static __device__ arrays per harness rules)
static __device__ unsigned char g_Q8[(size_t)NN * NN];  // 64 MB fp8 e4m3 Q (L2-resident)
static __device__ float g_colAccS[4][NN];               // sliced accumulators
static __device__ float g_V[NN];
static __device__ float g_U[NN];
static __device__ unsigned int g_minBits;
static __device__ double g_sum;
static __device__ double g_sumsq;
static __device__ float g_minv;
static __device__ float g_kscale;

// ---------------------------------------------------------------- helpers
__device__ __forceinline__ float2 f8x2_to_f2(unsigned int s) {
    __half2_raw hr = __nv_cvt_fp8x2_to_halfraw2((__nv_fp8x2_storage_t)s, __NV_E4M3);
    return __half22float2(*reinterpret_cast<__half2*>(&hr));
}

// dot of 16 fp8 values (one uint4) against 16 fp32 V entries
__device__ __forceinline__ float dot16f8(uint4 raw, const float* __restrict__ v) {
    float4 v0 = *reinterpret_cast<const float4*>(v);
    float4 v1 = *reinterpret_cast<const float4*>(v + 4);
    float4 v2 = *reinterpret_cast<const float4*>(v + 8);
    float4 v3 = *reinterpret_cast<const float4*>(v + 12);
    float2 a0 = f8x2_to_f2(raw.x & 0xffffu);
    float2 a1 = f8x2_to_f2(raw.x >> 16);
    float2 b0 = f8x2_to_f2(raw.y & 0xffffu);
    float2 b1 = f8x2_to_f2(raw.y >> 16);
    float2 c0 = f8x2_to_f2(raw.z & 0xffffu);
    float2 c1 = f8x2_to_f2(raw.z >> 16);
    float2 d0 = f8x2_to_f2(raw.w & 0xffffu);
    float2 d1 = f8x2_to_f2(raw.w >> 16);
    float r = a0.x * v0.x;
    r = fmaf(a0.y, v0.y, r);
    r = fmaf(a1.x, v0.z, r);
    r = fmaf(a1.y, v0.w, r);
    r = fmaf(b0.x, v1.x, r);
    r = fmaf(b0.y, v1.y, r);
    r = fmaf(b1.x, v1.z, r);
    r = fmaf(b1.y, v1.w, r);
    r = fmaf(c0.x, v2.x, r);
    r = fmaf(c0.y, v2.y, r);
    r = fmaf(c1.x, v2.z, r);
    r = fmaf(c1.y, v2.w, r);
    r = fmaf(d0.x, v3.x, r);
    r = fmaf(d0.y, v3.y, r);
    r = fmaf(d1.x, v3.z, r);
    r = fmaf(d1.y, v3.w, r);
    return r;
}

// ---------------------------------------------------------------- init
__global__ void k_init() {
    int i = blockIdx.x * blockDim.x + threadIdx.x;
    if (i < NN) {
        g_colAccS[0][i] = 0.0f;
        g_colAccS[1][i] = 0.0f;
        g_colAccS[2][i] = 0.0f;
        g_colAccS[3][i] = 0.0f;
    }
    if (i == 0) {
        g_minBits = 0x7f800000u;
        g_sum = 0.0;
        g_sumsq = 0.0;
    }
}

// ---------------------------------------------------------------- reduce: min / sum / sumsq
__global__ void __launch_bounds__(256) k_reduce(const float* __restrict__ c) {
    const size_t total4 = (size_t)NN * NN / 4;
    const size_t stride = (size_t)gridDim.x * blockDim.x;
    double s = 0.0, ss = 0.0;
    float mn = 3.402823466e38f;
    for (size_t i = (size_t)blockIdx.x * blockDim.x + threadIdx.x; i < total4; i += stride) {
        float4 v = reinterpret_cast<const float4*>(c)[i];
        float cs  = (v.x + v.y) + (v.z + v.w);
        float css = fmaf(v.x, v.x, fmaf(v.y, v.y, fmaf(v.z, v.z, v.w * v.w)));
        s  += (double)cs;
        ss += (double)css;
        mn = fminf(mn, fminf(fminf(v.x, v.y), fminf(v.z, v.w)));
    }
    for (int o = 16; o > 0; o >>= 1) {
        s  += __shfl_down_sync(0xffffffffu, s, o);
        ss += __shfl_down_sync(0xffffffffu, ss, o);
        mn = fminf(mn, __shfl_down_sync(0xffffffffu, mn, o));
    }
    __shared__ double sh_s[8], sh_ss[8];
    __shared__ float sh_m[8];
    int warp = threadIdx.x >> 5, lane = threadIdx.x & 31;
    if (lane == 0) { sh_s[warp] = s; sh_ss[warp] = ss; sh_m[warp] = mn; }
    __syncthreads();
    if (threadIdx.x < 8) {
        s = sh_s[threadIdx.x]; ss = sh_ss[threadIdx.x]; mn = sh_m[threadIdx.x];
        for (int o = 4; o > 0; o >>= 1) {
            s  += __shfl_down_sync(0xffu, s, o);
            ss += __shfl_down_sync(0xffu, ss, o);
            mn = fminf(mn, __shfl_down_sync(0xffu, mn, o));
        }
        if (threadIdx.x == 0) {
            atomicAdd(&g_sum, s);
            atomicAdd(&g_sumsq, ss);
            atomicMin(&g_minBits, __float_as_uint(mn));
        }
    }
}

// ---------------------------------------------------------------- scalar finalize
__global__ void k_scalars() {
    double n = (double)NN * (double)NN;
    double var = (g_sumsq - g_sum * g_sum / n) / (n - 1.0);
    float stdv = (float)sqrt(var);
    g_minv = __uint_as_float(g_minBits);
    g_kscale = 1.0f / (stdv * TEMPER);
}

// ---------------------------------------------------------------- build Q8 (fp8) + exact colsum
// grid (8, 128): x = 1024-col chunk, y = 64-row chunk; 4 cols/thread
__global__ void __launch_bounds__(256) k_build8(const float* __restrict__ c) {
    const float minv = g_minv, kk = g_kscale;
    int col0 = (blockIdx.x * 256 + threadIdx.x) * 4;
    int row0 = blockIdx.y * 64;
    float a0 = 0.f, a1 = 0.f, a2 = 0.f, a3 = 0.f;
    for (int r = 0; r < 64; ++r) {
        size_t base = (size_t)(row0 + r) * NN + col0;
        float4 v = *reinterpret_cast<const float4*>(c + base);
        float q0 = __expf((minv - v.x) * kk);
        float q1 = __expf((minv - v.y) * kk);
        float q2 = __expf((minv - v.z) * kk);
        float q3 = __expf((minv - v.w) * kk);
        a0 += q0; a1 += q1; a2 += q2; a3 += q3;
        float2 p0; p0.x = q0; p0.y = q1;
        float2 p1; p1.x = q2; p1.y = q3;
        unsigned int lo = __nv_cvt_float2_to_fp8x2(p0, __NV_SATFINITE, __NV_E4M3);
        unsigned int hi = __nv_cvt_float2_to_fp8x2(p1, __NV_SATFINITE, __NV_E4M3);
        *reinterpret_cast<unsigned int*>(g_Q8 + base) = (hi << 16) | (lo & 0xffffu);
    }
    float* ca = g_colAccS[blockIdx.y & 3];
    atomicAdd(&ca[col0 + 0], a0);
    atomicAdd(&ca[col0 + 1], a1);
    atomicAdd(&ca[col0 + 2], a2);
    atomicAdd(&ca[col0 + 3], a3);
}

// ---------------------------------------------------------------- V = B / sum(slices) ; slices = 0
__global__ void k_vfin(const float* __restrict__ B) {
    int j = blockIdx.x * blockDim.x + threadIdx.x;
    if (j < NN) {
        float s = (g_colAccS[0][j] + g_colAccS[1][j]) + (g_colAccS[2][j] + g_colAccS[3][j]);
        g_V[j] = B[j] / s;
        g_colAccS[0][j] = 0.0f;
        g_colAccS[1][j] = 0.0f;
        g_colAccS[2][j] = 0.0f;
        g_colAccS[3][j] = 0.0f;
    }
}

// ---------------------------------------------------------------- U = A / (Q8 V)
// 512 blocks x 512 threads; warp per row (16 rows/block); deep unroll for MLP
__global__ void __launch_bounds__(512) k_rowmv8(const float* __restrict__ A) {
    __shared__ float sV[NN];
    int tid = threadIdx.x;
#pragma unroll
    for (int i = 0; i < 4; ++i)
        reinterpret_cast<float4*>(sV)[tid + i * 512] =
            reinterpret_cast<const float4*>(g_V)[tid + i * 512];
    __syncthreads();
    int warp = tid >> 5, lane = tid & 31;
    int row = blockIdx.x * 16 + warp;
    const uint4* qr = reinterpret_cast<const uint4*>(g_Q8 + (size_t)row * NN) + lane;
    float acc = 0.f;
#pragma unroll
    for (int k = 0; k < 16; k += 8) {
        uint4 r[8];
#pragma unroll
        for (int u = 0; u < 8; ++u) r[u] = qr[(k + u) * 32];
#pragma unroll
        for (int u = 0; u < 8; ++u)
            acc += dot16f8(r[u], sV + lane * 16 + (k + u) * 512);
    }
    for (int o = 16; o > 0; o >>= 1)
        acc += __shfl_down_sync(0xffffffffu, acc, o);
    if (lane == 0) g_U[row] = __ldg(A + row) / acc;
}

// ---------------------------------------------------------------- slices += Q8^T U
// grid 1024: 128 row-chunks (64 rows) x 8 col-chunks (1024 cols); 4 cols/thread
__global__ void __launch_bounds__(256) k_colmv8() {
    __shared__ float sU[64];
    int tid = threadIdx.x;
    int rb = blockIdx.x >> 3;
    int col0 = (blockIdx.x & 7) * 1024 + tid * 4;
    int row0 = rb * 64;
    if (tid < 64) sU[tid] = g_U[row0 + tid];
    __syncthreads();
    const unsigned int* qp =
        reinterpret_cast<const unsigned int*>(g_Q8 + (size_t)row0 * NN + col0);
    float a0 = 0.f, a1 = 0.f, a2 = 0.f, a3 = 0.f;
#pragma unroll 8
    for (int r = 0; r < 64; ++r) {
        unsigned int w = qp[(size_t)r * (NN / 4)];
        float u = sU[r];
        float2 lo = f8x2_to_f2(w & 0xffffu);
        float2 hi = f8x2_to_f2(w >> 16);
        a0 = fmaf(lo.x, u, a0);
        a1 = fmaf(lo.y, u, a1);
        a2 = fmaf(hi.x, u, a2);
        a3 = fmaf(hi.y, u, a3);
    }
    float* ca = g_colAccS[rb & 3];
    atomicAdd(&ca[col0 + 0], a0);
    atomicAdd(&ca[col0 + 1], a1);
    atomicAdd(&ca[col0 + 2], a2);
    atomicAdd(&ca[col0 + 3], a3);
}

// ---------------------------------------------------------------- exact colmv (for V10): slices += Q^T U, Q from cdist
__global__ void __launch_bounds__(256) k_colmv_exact(const float* __restrict__ c) {
    __shared__ float sU[64];
    int tid = threadIdx.x;
    int rb = blockIdx.x >> 3;
    int col0 = (blockIdx.x & 7) * 1024 + tid * 4;
    int row0 = rb * 64;
    if (tid < 64) sU[tid] = g_U[row0 + tid];
    __syncthreads();
    const float minv = g_minv, kk = g_kscale;
    const float* cp = c + (size_t)row0 * NN + col0;
    float a0 = 0.f, a1 = 0.f, a2 = 0.f, a3 = 0.f;
#pragma unroll 4
    for (int r = 0; r < 64; ++r) {
        float4 v = *reinterpret_cast<const float4*>(cp + (size_t)r * NN);
        float u = sU[r];
        a0 = fmaf(__expf((minv - v.x) * kk), u, a0);
        a1 = fmaf(__expf((minv - v.y) * kk), u, a1);
        a2 = fmaf(__expf((minv - v.z) * kk), u, a2);
        a3 = fmaf(__expf((minv - v.w) * kk), u, a3);
    }
    float* ca = g_colAccS[rb & 3];
    atomicAdd(&ca[col0 + 0], a0);
    atomicAdd(&ca[col0 + 1], a1);
    atomicAdd(&ca[col0 + 2], a2);
    atomicAdd(&ca[col0 + 3], a3);
}

// ---------------------------------------------------------------- final: exact Q, fused U10, write T
__global__ void __launch_bounds__(256) k_final(const float* __restrict__ c,
                                               const float* __restrict__ A,
                                               float* __restrict__ out) {
    __shared__ float sV[NN];
    __shared__ float sred[8];
    __shared__ float sbc;
    int tid = threadIdx.x;
#pragma unroll
    for (int i = 0; i < 8; ++i)
        reinterpret_cast<float4*>(sV)[tid + i * 256] =
            reinterpret_cast<const float4*>(g_V)[tid + i * 256];
    __syncthreads();
    const float minv = g_minv, kk = g_kscale;
    for (int row = blockIdx.x; row < NN; row += gridDim.x) {
        const float4* crow = reinterpret_cast<const float4*>(c + (size_t)row * NN);
        float4 qv[8];
        float s = 0.f;
#pragma unroll
        for (int k = 0; k < 8; ++k) {
            int j = tid * 4 + k * 1024;
            float4 v  = crow[tid + k * 256];
            float4 vv = *reinterpret_cast<const float4*>(sV + j);
            float q0 = __expf((minv - v.x) * kk) * vv.x;
            float q1 = __expf((minv - v.y) * kk) * vv.y;
            float q2 = __expf((minv - v.z) * kk) * vv.z;
            float q3 = __expf((minv - v.w) * kk) * vv.w;
            qv[k].x = q0; qv[k].y = q1; qv[k].z = q2; qv[k].w = q3;
            s += (q0 + q1) + (q2 + q3);
        }
        for (int o = 16; o > 0; o >>= 1)
            s += __shfl_down_sync(0xffffffffu, s, o);
        if ((tid & 31) == 0) sred[tid >> 5] = s;
        __syncthreads();
        if (tid < 32) {
            float t = (tid < 8) ? sred[tid] : 0.f;
            for (int o = 4; o > 0; o >>= 1)
                t += __shfl_down_sync(0xffffffffu, t, o);
            if (tid == 0) sbc = __ldg(A + row) / t;
        }
        __syncthreads();
        float scale = sbc;
        float4* orow = reinterpret_cast<float4*>(out + (size_t)row * NN);
#pragma unroll
        for (int k = 0; k < 8; ++k) {
            float4 w = qv[k];
            w.x *= scale; w.y *= scale; w.z *= scale; w.w *= scale;
            orow[tid + k * 256] = w;
        }
        __syncthreads();
    }
}

// ---------------------------------------------------------------- launch
extern "C" void kernel_launch(void* const* d_in, const int* in_sizes, int n_in,
                              void* d_out, int out_size) {
    const float* cdist = (const float*)d_in[0];
    const float* A     = (const float*)d_in[1];
    const float* B     = (const float*)d_in[2];
    float* out = (float*)d_out;

    k_init<<<32, 256>>>();
    k_reduce<<<1184, 256>>>(cdist);
    k_scalars<<<1, 1>>>();
    k_build8<<<dim3(8, 128), 256>>>(cdist);  // Q8 (fp8), exact colsum -> slices
    k_vfin<<<32, 256>>>(B);                  // V1
    for (int it = 1; it <= 8; ++it) {
        k_rowmv8<<<512, 512>>>(A);           // U_it = A/(Q8 V_it)
        k_colmv8<<<1024, 256>>>();           // slices = Q8^T U_it
        k_vfin<<<32, 256>>>(B);              // V_{it+1}
    }
    k_rowmv8<<<512, 512>>>(A);               // U9 (fp8, error damped by next step)
    k_colmv_exact<<<1024, 256>>>(cdist);     // slices = Q^T U9 (exact)
    k_vfin<<<32, 256>>>(B);                  // V10 (accurate)
    // U10 fused into output: exact fp32 Q, T = (A_i/(Q V10)_i) * Q_ij * V10_j
    k_final<<<444, 256>>>(cdist, A, out);
}

// round 4
// speedup vs baseline: 3.2030x; 1.4595x over previous
#include <cuda_runtime.h>
#include <cuda_bf16.h>
#include <cuda_fp8.h>

#define NN 8192
#define TEMPER 0.2f

// Scratch (static __device__ arrays per harness rules)
static __device__ unsigned char g_Q8[(size_t)NN * NN];  // 64 MB fp8 e4m3 Q (L2-resident)
static __device__ float g_colAccS[4][NN];               // sliced accumulators
static __device__ float g_V[NN];
static __device__ float g_U[NN];
static __device__ unsigned int g_minBits;
static __device__ double g_sum;
static __device__ double g_sumsq;
static __device__ float g_minv;
static __device__ float g_kscale;

// ---------------------------------------------------------------- helpers
__device__ __forceinline__ float2 f8x2_to_f2(unsigned int s) {
    __half2_raw hr = __nv_cvt_fp8x2_to_halfraw2((__nv_fp8x2_storage_t)s, __NV_E4M3);
    return __half22float2(*reinterpret_cast<__half2*>(&hr));
}

// ---------------------------------------------------------------- init
__global__ void k_init() {
    int i = blockIdx.x * blockDim.x + threadIdx.x;
    if (i < NN) {
        g_colAccS[0][i] = 0.0f;
        g_colAccS[1][i] = 0.0f;
        g_colAccS[2][i] = 0.0f;
        g_colAccS[3][i] = 0.0f;
    }
    if (i == 0) {
        g_minBits = 0x7f800000u;
        g_sum = 0.0;
        g_sumsq = 0.0;
    }
}

// ---------------------------------------------------------------- reduce: min / sum / sumsq
__global__ void __launch_bounds__(256) k_reduce(const float* __restrict__ c) {
    const size_t total4 = (size_t)NN * NN / 4;
    const size_t stride = (size_t)gridDim.x * blockDim.x;
    double s = 0.0, ss = 0.0;
    float mn = 3.402823466e38f;
    for (size_t i = (size_t)blockIdx.x * blockDim.x + threadIdx.x; i < total4; i += stride) {
        float4 v = reinterpret_cast<const float4*>(c)[i];
        float cs  = (v.x + v.y) + (v.z + v.w);
        float css = fmaf(v.x, v.x, fmaf(v.y, v.y, fmaf(v.z, v.z, v.w * v.w)));
        s  += (double)cs;
        ss += (double)css;
        mn = fminf(mn, fminf(fminf(v.x, v.y), fminf(v.z, v.w)));
    }
    for (int o = 16; o > 0; o >>= 1) {
        s  += __shfl_down_sync(0xffffffffu, s, o);
        ss += __shfl_down_sync(0xffffffffu, ss, o);
        mn = fminf(mn, __shfl_down_sync(0xffffffffu, mn, o));
    }
    __shared__ double sh_s[8], sh_ss[8];
    __shared__ float sh_m[8];
    int warp = threadIdx.x >> 5, lane = threadIdx.x & 31;
    if (lane == 0) { sh_s[warp] = s; sh_ss[warp] = ss; sh_m[warp] = mn; }
    __syncthreads();
    if (threadIdx.x < 8) {
        s = sh_s[threadIdx.x]; ss = sh_ss[threadIdx.x]; mn = sh_m[threadIdx.x];
        for (int o = 4; o > 0; o >>= 1) {
            s  += __shfl_down_sync(0xffu, s, o);
            ss += __shfl_down_sync(0xffu, ss, o);
            mn = fminf(mn, __shfl_down_sync(0xffu, mn, o));
        }
        if (threadIdx.x == 0) {
            atomicAdd(&g_sum, s);
            atomicAdd(&g_sumsq, ss);
            atomicMin(&g_minBits, __float_as_uint(mn));
        }
    }
}

// ---------------------------------------------------------------- scalar finalize
__global__ void k_scalars() {
    double n = (double)NN * (double)NN;
    double var = (g_sumsq - g_sum * g_sum / n) / (n - 1.0);
    float stdv = (float)sqrt(var);
    g_minv = __uint_as_float(g_minBits);
    g_kscale = 1.0f / (stdv * TEMPER);
}

// ---------------------------------------------------------------- build Q8 (fp8) + exact colsum
// grid (8, 128): x = 1024-col chunk, y = 64-row chunk; 4 cols/thread
__global__ void __launch_bounds__(256) k_build8(const float* __restrict__ c) {
    const float minv = g_minv, kk = g_kscale;
    int col0 = (blockIdx.x * 256 + threadIdx.x) * 4;
    int row0 = blockIdx.y * 64;
    float a0 = 0.f, a1 = 0.f, a2 = 0.f, a3 = 0.f;
    for (int r = 0; r < 64; ++r) {
        size_t base = (size_t)(row0 + r) * NN + col0;
        float4 v = *reinterpret_cast<const float4*>(c + base);
        float q0 = __expf((minv - v.x) * kk);
        float q1 = __expf((minv - v.y) * kk);
        float q2 = __expf((minv - v.z) * kk);
        float q3 = __expf((minv - v.w) * kk);
        a0 += q0; a1 += q1; a2 += q2; a3 += q3;
        float2 p0; p0.x = q0; p0.y = q1;
        float2 p1; p1.x = q2; p1.y = q3;
        unsigned int lo = __nv_cvt_float2_to_fp8x2(p0, __NV_SATFINITE, __NV_E4M3);
        unsigned int hi = __nv_cvt_float2_to_fp8x2(p1, __NV_SATFINITE, __NV_E4M3);
        *reinterpret_cast<unsigned int*>(g_Q8 + base) = (hi << 16) | (lo & 0xffffu);
    }
    float* ca = g_colAccS[blockIdx.y & 3];
    atomicAdd(&ca[col0 + 0], a0);
    atomicAdd(&ca[col0 + 1], a1);
    atomicAdd(&ca[col0 + 2], a2);
    atomicAdd(&ca[col0 + 3], a3);
}

// ---------------------------------------------------------------- V = B / sum(slices) ; slices = 0
__global__ void k_vfin(const float* __restrict__ B) {
    int j = blockIdx.x * blockDim.x + threadIdx.x;
    if (j < NN) {
        float s = (g_colAccS[0][j] + g_colAccS[1][j]) + (g_colAccS[2][j] + g_colAccS[3][j]);
        g_V[j] = B[j] / s;
        g_colAccS[0][j] = 0.0f;
        g_colAccS[1][j] = 0.0f;
        g_colAccS[2][j] = 0.0f;
        g_colAccS[3][j] = 0.0f;
    }
}

// ---------------------------------------------------------------- U = A / (Q8 V)
// 512 blocks x 256 threads; 8 warps; each warp handles 2 rows (shared V read).
// Lane owns 4 consecutive fp8 per step -> conflict-free float4 SMEM reads (lane stride 4 words).
__global__ void __launch_bounds__(256) k_rowmv8(const float* __restrict__ A) {
    __shared__ float sV[NN];
    int tid = threadIdx.x;
#pragma unroll
    for (int i = 0; i < 8; ++i)
        reinterpret_cast<float4*>(sV)[tid + i * 256] =
            reinterpret_cast<const float4*>(g_V)[tid + i * 256];
    __syncthreads();
    int warp = tid >> 5, lane = tid & 31;
    int row0 = blockIdx.x * 16 + warp * 2;
    const unsigned int* q0 = reinterpret_cast<const unsigned int*>(g_Q8 + (size_t)row0 * NN);
    const unsigned int* q1 = reinterpret_cast<const unsigned int*>(g_Q8 + (size_t)(row0 + 1) * NN);
    const float4* v4 = reinterpret_cast<const float4*>(sV);
    float acc0 = 0.f, acc1 = 0.f;
    // 8192 cols / (4 per uint * 32 lanes) = 64 steps; batch 4 steps x 2 rows = 8 loads in flight
#pragma unroll
    for (int s = 0; s < 64; s += 4) {
        unsigned int a[4], b[4];
#pragma unroll
        for (int u = 0; u < 4; ++u) {
            a[u] = q0[lane + (s + u) * 32];
            b[u] = q1[lane + (s + u) * 32];
        }
#pragma unroll
        for (int u = 0; u < 4; ++u) {
            float4 v = v4[lane + (s + u) * 32];
            float2 lo = f8x2_to_f2(a[u] & 0xffffu);
            float2 hi = f8x2_to_f2(a[u] >> 16);
            acc0 = fmaf(lo.x, v.x, acc0);
            acc0 = fmaf(lo.y, v.y, acc0);
            acc0 = fmaf(hi.x, v.z, acc0);
            acc0 = fmaf(hi.y, v.w, acc0);
            float2 lo1 = f8x2_to_f2(b[u] & 0xffffu);
            float2 hi1 = f8x2_to_f2(b[u] >> 16);
            acc1 = fmaf(lo1.x, v.x, acc1);
            acc1 = fmaf(lo1.y, v.y, acc1);
            acc1 = fmaf(hi1.x, v.z, acc1);
            acc1 = fmaf(hi1.y, v.w, acc1);
        }
    }
    for (int o = 16; o > 0; o >>= 1) {
        acc0 += __shfl_down_sync(0xffffffffu, acc0, o);
        acc1 += __shfl_down_sync(0xffffffffu, acc1, o);
    }
    if (lane == 0) {
        g_U[row0]     = __ldg(A + row0) / acc0;
        g_U[row0 + 1] = __ldg(A + row0 + 1) / acc1;
    }
}

// ---------------------------------------------------------------- slices += Q8^T U
// grid 1024: 128 row-chunks (64 rows) x 8 col-chunks (1024 cols); 4 cols/thread
__global__ void __launch_bounds__(256) k_colmv8() {
    __shared__ float sU[64];
    int tid = threadIdx.x;
    int rb = blockIdx.x >> 3;
    int col0 = (blockIdx.x & 7) * 1024 + tid * 4;
    int row0 = rb * 64;
    if (tid < 64) sU[tid] = g_U[row0 + tid];
    __syncthreads();
    const unsigned int* qp =
        reinterpret_cast<const unsigned int*>(g_Q8 + (size_t)row0 * NN + col0);
    float a0 = 0.f, a1 = 0.f, a2 = 0.f, a3 = 0.f;
#pragma unroll 8
    for (int r = 0; r < 64; ++r) {
        unsigned int w = qp[(size_t)r * (NN / 4)];
        float u = sU[r];
        float2 lo = f8x2_to_f2(w & 0xffffu);
        float2 hi = f8x2_to_f2(w >> 16);
        a0 = fmaf(lo.x, u, a0);
        a1 = fmaf(lo.y, u, a1);
        a2 = fmaf(hi.x, u, a2);
        a3 = fmaf(hi.y, u, a3);
    }
    float* ca = g_colAccS[rb & 3];
    atomicAdd(&ca[col0 + 0], a0);
    atomicAdd(&ca[col0 + 1], a1);
    atomicAdd(&ca[col0 + 2], a2);
    atomicAdd(&ca[col0 + 3], a3);
}

// ---------------------------------------------------------------- exact colmv (for V10): slices += Q^T U, Q from cdist
__global__ void __launch_bounds__(256) k_colmv_exact(const float* __restrict__ c) {
    __shared__ float sU[64];
    int tid = threadIdx.x;
    int rb = blockIdx.x >> 3;
    int col0 = (blockIdx.x & 7) * 1024 + tid * 4;
    int row0 = rb * 64;
    if (tid < 64) sU[tid] = g_U[row0 + tid];
    __syncthreads();
    const float minv = g_minv, kk = g_kscale;
    const float* cp = c + (size_t)row0 * NN + col0;
    float a0 = 0.f, a1 = 0.f, a2 = 0.f, a3 = 0.f;
#pragma unroll 4
    for (int r = 0; r < 64; ++r) {
        float4 v = *reinterpret_cast<const float4*>(cp + (size_t)r * NN);
        float u = sU[r];
        a0 = fmaf(__expf((minv - v.x) * kk), u, a0);
        a1 = fmaf(__expf((minv - v.y) * kk), u, a1);
        a2 = fmaf(__expf((minv - v.z) * kk), u, a2);
        a3 = fmaf(__expf((minv - v.w) * kk), u, a3);
    }
    float* ca = g_colAccS[rb & 3];
    atomicAdd(&ca[col0 + 0], a0);
    atomicAdd(&ca[col0 + 1], a1);
    atomicAdd(&ca[col0 + 2], a2);
    atomicAdd(&ca[col0 + 3], a3);
}

// ---------------------------------------------------------------- final: exact Q, fused U10, write T
__global__ void __launch_bounds__(256) k_final(const float* __restrict__ c,
                                               const float* __restrict__ A,
                                               float* __restrict__ out) {
    __shared__ float sV[NN];
    __shared__ float sred[8];
    __shared__ float sbc;
    int tid = threadIdx.x;
#pragma unroll
    for (int i = 0; i < 8; ++i)
        reinterpret_cast<float4*>(sV)[tid + i * 256] =
            reinterpret_cast<const float4*>(g_V)[tid + i * 256];
    __syncthreads();
    const float minv = g_minv, kk = g_kscale;
    for (int row = blockIdx.x; row < NN; row += gridDim.x) {
        const float4* crow = reinterpret_cast<const float4*>(c + (size_t)row * NN);
        float4 qv[8];
        float s = 0.f;
#pragma unroll
        for (int k = 0; k < 8; ++k) {
            int j = tid * 4 + k * 1024;
            float4 v  = crow[tid + k * 256];
            float4 vv = *reinterpret_cast<const float4*>(sV + j);
            float q0 = __expf((minv - v.x) * kk) * vv.x;
            float q1 = __expf((minv - v.y) * kk) * vv.y;
            float q2 = __expf((minv - v.z) * kk) * vv.z;
            float q3 = __expf((minv - v.w) * kk) * vv.w;
            qv[k].x = q0; qv[k].y = q1; qv[k].z = q2; qv[k].w = q3;
            s += (q0 + q1) + (q2 + q3);
        }
        for (int o = 16; o > 0; o >>= 1)
            s += __shfl_down_sync(0xffffffffu, s, o);
        if ((tid & 31) == 0) sred[tid >> 5] = s;
        __syncthreads();
        if (tid < 32) {
            float t = (tid < 8) ? sred[tid] : 0.f;
            for (int o = 4; o > 0; o >>= 1)
                t += __shfl_down_sync(0xffffffffu, t, o);
            if (tid == 0) sbc = __ldg(A + row) / t;
        }
        __syncthreads();
        float scale = sbc;
        float4* orow = reinterpret_cast<float4*>(out + (size_t)row * NN);
#pragma unroll
        for (int k = 0; k < 8; ++k) {
            float4 w = qv[k];
            w.x *= scale; w.y *= scale; w.z *= scale; w.w *= scale;
            orow[tid + k * 256] = w;
        }
        __syncthreads();
    }
}

// ---------------------------------------------------------------- launch
extern "C" void kernel_launch(void* const* d_in, const int* in_sizes, int n_in,
                              void* d_out, int out_size) {
    const float* cdist = (const float*)d_in[0];
    const float* A     = (const float*)d_in[1];
    const float* B     = (const float*)d_in[2];
    float* out = (float*)d_out;

    k_init<<<32, 256>>>();
    k_reduce<<<1184, 256>>>(cdist);
    k_scalars<<<1, 1>>>();
    k_build8<<<dim3(8, 128), 256>>>(cdist);  // Q8 (fp8), exact colsum -> slices
    k_vfin<<<32, 256>>>(B);                  // V1
    for (int it = 1; it <= 8; ++it) {
        k_rowmv8<<<512, 256>>>(A);           // U_it = A/(Q8 V_it)
        k_colmv8<<<1024, 256>>>();           // slices = Q8^T U_it
        k_vfin<<<32, 256>>>(B);              // V_{it+1}
    }
    k_rowmv8<<<512, 256>>>(A);               // U9 (fp8, error damped by next step)
    k_colmv_exact<<<1024, 256>>>(cdist);     // slices = Q^T U9 (exact)
    k_vfin<<<32, 256>>>(B);                  // V10 (accurate)
    // U10 fused into output: exact fp32 Q, T = (A_i/(Q V10)_i) * Q_ij * V10_j
    k_final<<<444, 256>>>(cdist, A, out);
}